// round 12
// baseline (speedup 1.0000x reference)
#include <cuda_runtime.h>
#include <cuda_bf16.h>
#include <cstdint>
#include <math.h>

#define NH     16
#define NSEQ   8192
#define EDIM   64
#define CHUNKN 512
#define NCH    16
#define WCOLS  15872
#define MTILE  128
#define SCALE  0.125f

// ---- bf16 hi/lo scratch planes: [0]=Khi [1]=Klo [2]=Vhi [3]=Vlo ----
#define SCR_ELEMS (16u * 8192u * 64u)   // 8388608
__device__ __nv_bfloat16 g_scr[4][SCR_ELEMS];

// ---- SMEM layout (rows stride 144B = 64 bf16 + 8 pad) ----
// Q: 128 rows, hi @0 lo @+18432.  K/V slabs: 64 rows, hi @+0 lo @+9216.
#define SM_Q     0
#define SM_K0    36864
#define SM_K1    55296
#define SM_V0    73728
#define SM_V1    92160
#define SM_WS    110592         // 8 warps x 16 inv fp32 = 512B
#define SM_TOTAL 111104

__device__ __forceinline__ uint32_t s2u(const void* p) {
    uint32_t a;
    asm("{ .reg .u64 t; cvta.to.shared.u64 t, %1; cvt.u32.u64 %0, t; }" : "=r"(a) : "l"(p));
    return a;
}
__device__ __forceinline__ void ldmx4(uint32_t addr, uint32_t* r) {
    asm volatile("ldmatrix.sync.aligned.m8n8.x4.shared.b16 {%0,%1,%2,%3}, [%4];"
                 : "=r"(r[0]), "=r"(r[1]), "=r"(r[2]), "=r"(r[3]) : "r"(addr));
}
__device__ __forceinline__ void ldmx2(uint32_t addr, uint32_t* r) {
    asm volatile("ldmatrix.sync.aligned.m8n8.x2.shared.b16 {%0,%1}, [%2];"
                 : "=r"(r[0]), "=r"(r[1]) : "r"(addr));
}
__device__ __forceinline__ void ldmx2t(uint32_t addr, uint32_t* r) {
    asm volatile("ldmatrix.sync.aligned.m8n8.x2.trans.shared.b16 {%0,%1}, [%2];"
                 : "=r"(r[0]), "=r"(r[1]) : "r"(addr));
}
__device__ __forceinline__ void mma16816(float* d, const uint32_t* a, const uint32_t* b) {
    asm volatile("mma.sync.aligned.m16n8k16.row.col.f32.bf16.bf16.f32 "
                 "{%0,%1,%2,%3},{%4,%5,%6,%7},{%8,%9},{%0,%1,%2,%3};"
                 : "+f"(d[0]), "+f"(d[1]), "+f"(d[2]), "+f"(d[3])
                 : "r"(a[0]), "r"(a[1]), "r"(a[2]), "r"(a[3]), "r"(b[0]), "r"(b[1]));
}
__device__ __forceinline__ uint32_t packbf(float lo, float hi) {
    uint32_t r;
    asm("cvt.rn.bf16x2.f32 %0, %1, %2;" : "=r"(r) : "f"(hi), "f"(lo));
    return r;
}
__device__ __forceinline__ float bfval(float x) {
    return __bfloat162float(__float2bfloat16(x));
}
__device__ __forceinline__ void cpa16(uint32_t dst, const void* src) {
    asm volatile("cp.async.cg.shared.global [%0], [%1], 16;" :: "r"(dst), "l"(src));
}
#define CP_COMMIT() asm volatile("cp.async.commit_group;" ::: "memory")
#define CP_WAIT(n)  asm volatile("cp.async.wait_group %0;" :: "n"(n) : "memory")

// =================== pre-kernel: fp32 -> bf16 hi/lo planes ===================
__global__ __launch_bounds__(512)
void convert_kv(const float* __restrict__ key, const float* __restrict__ value)
{
    uint32_t i = blockIdx.x * 512u + threadIdx.x;      // float4 index, exact grid
    float4 kv = ((const float4*)key)[i];
    float4 vv = ((const float4*)value)[i];
    uint2 khi, klo, vhi, vlo;
    khi.x = packbf(kv.x, kv.y); khi.y = packbf(kv.z, kv.w);
    klo.x = packbf(kv.x - bfval(kv.x), kv.y - bfval(kv.y));
    klo.y = packbf(kv.z - bfval(kv.z), kv.w - bfval(kv.w));
    vhi.x = packbf(vv.x, vv.y); vhi.y = packbf(vv.z, vv.w);
    vlo.x = packbf(vv.x - bfval(vv.x), vv.y - bfval(vv.y));
    vlo.y = packbf(vv.z - bfval(vv.z), vv.w - bfval(vv.w));
    ((uint2*)g_scr[0])[i] = khi;
    ((uint2*)g_scr[1])[i] = klo;
    ((uint2*)g_scr[2])[i] = vhi;
    ((uint2*)g_scr[3])[i] = vlo;
}

// =================== main kernel: 256 threads, 2 CTAs/SM, warp-autonomous strips ===================
__global__ __launch_bounds__(256, 2)
void chunked_attn_mma(const float* __restrict__ query, float* __restrict__ out,
                      float* __restrict__ wts)
{
    extern __shared__ char smem[];
    const uint32_t sb = s2u(smem);
    const int tid = threadIdx.x, lane = tid & 31, w = tid >> 5;   // w = strip 0..7

    const int rt = 3 - blockIdx.x;    // long CTAs first
    const int n  = blockIdx.y, h = blockIdx.z;
    const int r0 = rt * MTILE;
    const int m  = (n == 0) ? 0 : n - 1;
    const int nslab = 2 * (rt + 1);       // 64-key slabs
    const int jend  = 64 * nslab;
    const int wcb   = (n == 0) ? 0 : 512 + (n - 1) * 1024;

    const float* qbase = query + ((size_t)h * NSEQ + (size_t)n * CHUNKN + r0) * EDIM;
    const uint32_t gjbase = (uint32_t)h * NSEQ + (uint32_t)m * CHUNKN;   // key-row base

    const uint32_t kbuf[2] = {sb + SM_K0, sb + SM_K1};
    const uint32_t vbuf[2] = {sb + SM_V0, sb + SM_V1};

    // ---- prefetch slab 0: 4 planes x 64 rows x 128B = 2048 x 16B ----
    for (int i = tid; i < 2048; i += 256) {
        int arr = i >> 9, rem = i & 511, row = rem >> 3, seg = rem & 7;
        uint32_t base = (arr < 2) ? kbuf[0] : vbuf[0];
        uint32_t dst = base + ((arr & 1) ? 9216u : 0u) + (uint32_t)row * 144 + seg * 16;
        const __nv_bfloat16* src = g_scr[arr] + ((size_t)(gjbase + row) << 6) + seg * 8;
        cpa16(dst, src);
    }
    CP_COMMIT();

    // ---- zero-fill dead weight cols (warp-local rows) ----
    {
        const float4 z4 = make_float4(0.f, 0.f, 0.f, 0.f);
        for (int rr = 0; rr < 16; rr++) {
            float* wr = wts + ((size_t)h * CHUNKN + r0 + w * 16 + rr) * WCOLS + wcb;
            for (int c = jend + lane * 4; c < 512; c += 128) *(float4*)(wr + c) = z4;
            if (n > 0)
                for (int c = 512 + lane * 4; c < 1024; c += 128) *(float4*)(wr + c) = z4;
        }
    }

    // ---- Q fill: bf16 hi/lo, pre-scaled ----
    for (int idx = tid; idx < MTILE * 16; idx += 256) {
        int row = idx >> 4, c4 = (idx & 15) << 2;
        float4 qv = *(const float4*)(qbase + (size_t)row * EDIM + c4);
        float f[4] = {qv.x * SCALE, qv.y * SCALE, qv.z * SCALE, qv.w * SCALE};
        uint2 hv, lv;
        hv.x = packbf(f[0], f[1]); hv.y = packbf(f[2], f[3]);
        lv.x = packbf(f[0] - bfval(f[0]), f[1] - bfval(f[1]));
        lv.y = packbf(f[2] - bfval(f[2]), f[3] - bfval(f[3]));
        uint32_t o = (uint32_t)row * 144 + (uint32_t)c4 * 2;
        *(uint2*)(smem + SM_Q + o) = hv;
        *(uint2*)(smem + SM_Q + 18432 + o) = lv;
    }
    __syncthreads();   // Q visible

    float oacc[8][4];
    #pragma unroll
    for (int t = 0; t < 8; t++)
        #pragma unroll
        for (int u = 0; u < 4; u++) oacc[t][u] = 0.f;
    float rs0 = 0.f, rs1 = 0.f;

    const int rlo = r0 + w * 16 + (lane >> 2);
    const int rhi = rlo + 8;
    const uint32_t aQ = sb + SM_Q + (uint32_t)((w * 16 + (lane & 15)) * 144 + (lane >> 4) * 16);
    const uint32_t bKoff = (uint32_t)((lane & 7) * 144 + ((lane >> 3) & 1) * 16);
    const uint32_t bVoff = (uint32_t)((lane & 15) * 144);

    for (int kt = 0; kt < nslab; kt++) {
        const int p = kt & 1;
        if (kt + 1 < nslab) {   // prefetch next slab
            for (int i = tid; i < 2048; i += 256) {
                int arr = i >> 9, rem = i & 511, row = rem >> 3, seg = rem & 7;
                uint32_t base = (arr < 2) ? kbuf[1 - p] : vbuf[1 - p];
                uint32_t dst = base + ((arr & 1) ? 9216u : 0u) + (uint32_t)row * 144 + seg * 16;
                const __nv_bfloat16* src =
                    g_scr[arr] + ((size_t)(gjbase + (kt + 1) * 64 + row) << 6) + seg * 8;
                cpa16(dst, src);
            }
            CP_COMMIT();
            CP_WAIT(1);
        } else {
            CP_WAIT(0);
        }
        __syncthreads();        // slab p complete for all warps

        const bool dead = (kt * 64 > r0 + w * 16 + 15);
        const uint32_t bK = kbuf[p] + bKoff;
        const uint32_t bV = vbuf[p] + bVoff;

        // ---- GEMM1: S strip = Q(strip) . K(64)^T, bf16x3 ----
        float sacc[8][4];
        #pragma unroll
        for (int t = 0; t < 8; t++)
            #pragma unroll
            for (int u = 0; u < 4; u++) sacc[t][u] = 0.f;

        if (!dead) {
            #pragma unroll
            for (int kc = 0; kc < 4; kc++) {
                uint32_t qh[4], ql[4];
                ldmx4(aQ + kc * 32, qh);
                ldmx4(aQ + 18432 + kc * 32, ql);
                #pragma unroll
                for (int t = 0; t < 8; t++) {
                    uint32_t bh[2], bl[2];
                    uint32_t ba = bK + (uint32_t)t * 1152 + kc * 32;
                    ldmx2(ba, bh);
                    ldmx2(ba + 9216, bl);
                    mma16816(sacc[t], qh, bh);
                    mma16816(sacc[t], qh, bl);
                    mma16816(sacc[t], ql, bh);
                }
            }
        }

        // ---- per t: exp + mask + weights STG + pack; GEMM2 per 16-key pair ----
        const int cbase = kt * 64 + 2 * (lane & 3);
        float* wlo = wts + ((size_t)h * CHUNKN + rlo) * WCOLS + wcb + cbase;
        float* whi = wlo + (size_t)8 * WCOLS;
        uint32_t phi[2][2], plo[2][2];
        #pragma unroll
        for (int t = 0; t < 8; t++) {
            int c = cbase + t * 8;
            float p00 = (c     <= rlo) ? __expf(sacc[t][0]) : 0.f;
            float p01 = (c + 1 <= rlo) ? __expf(sacc[t][1]) : 0.f;
            float p10 = (c     <= rhi) ? __expf(sacc[t][2]) : 0.f;
            float p11 = (c + 1 <= rhi) ? __expf(sacc[t][3]) : 0.f;
            rs0 += p00 + p01;  rs1 += p10 + p11;
            *(float2*)(wlo + t * 8) = make_float2(p00, p01);
            *(float2*)(whi + t * 8) = make_float2(p10, p11);
            const int ti = t & 1;
            phi[ti][0] = packbf(p00, p01);
            phi[ti][1] = packbf(p10, p11);
            plo[ti][0] = packbf(p00 - bfval(p00), p01 - bfval(p01));
            plo[ti][1] = packbf(p10 - bfval(p10), p11 - bfval(p11));

            if (ti == 1 && !dead) {     // GEMM2 over this 16-key step
                uint32_t ah[4] = {phi[0][0], phi[0][1], phi[1][0], phi[1][1]};
                uint32_t al[4] = {plo[0][0], plo[0][1], plo[1][0], plo[1][1]};
                #pragma unroll
                for (int t2 = 0; t2 < 8; t2++) {
                    uint32_t bh[2], bl[2];
                    uint32_t ba = bV + (uint32_t)(t >> 1) * 2304 + t2 * 16;
                    ldmx2t(ba, bh);
                    ldmx2t(ba + 9216, bl);
                    mma16816(oacc[t2], ah, bh);
                    mma16816(oacc[t2], ah, bl);
                    mma16816(oacc[t2], al, bh);
                }
            }
        }
        __syncthreads();   // all reads of buf p done before refill
    }

    // ---- warp-local epilogue: rowsums, O write, weight rescale (no CTA barriers) ----
    rs0 += __shfl_xor_sync(0xffffffffu, rs0, 1);
    rs0 += __shfl_xor_sync(0xffffffffu, rs0, 2);
    rs1 += __shfl_xor_sync(0xffffffffu, rs1, 1);
    rs1 += __shfl_xor_sync(0xffffffffu, rs1, 2);
    const float inv0 = 1.f / rs0, inv1 = 1.f / rs1;

    {
        float* op = out + ((size_t)h * NSEQ + (size_t)n * CHUNKN + rlo) * EDIM;
        #pragma unroll
        for (int t2 = 0; t2 < 8; t2++) {
            int c = t2 * 8 + 2 * (lane & 3);
            *(float2*)(op + c) = make_float2(oacc[t2][0] * inv0, oacc[t2][1] * inv0);
            *(float2*)(op + (size_t)8 * EDIM + c) =
                make_float2(oacc[t2][2] * inv1, oacc[t2][3] * inv1);
        }
    }

    // stash per-row inv in warp-private smem, then rescale owned rows
    {
        float* wsm = (float*)(smem + SM_WS) + w * 16;
        if ((lane & 3) == 0) {
            wsm[lane >> 2]     = inv0;
            wsm[(lane >> 2) + 8] = inv1;
        }
        __syncwarp();
        for (int rr = 0; rr < 16; rr++) {
            float iv = wsm[rr];
            float* wr = wts + ((size_t)h * CHUNKN + r0 + w * 16 + rr) * WCOLS + wcb;
            for (int c = lane * 4; c < jend; c += 128) {
                float4 t = *(float4*)(wr + c);
                t.x *= iv; t.y *= iv; t.z *= iv; t.w *= iv;
                *(float4*)(wr + c) = t;
            }
        }
    }
}

extern "C" void kernel_launch(void* const* d_in, const int* in_sizes, int n_in,
                              void* d_out, int out_size)
{
    const float* q = (const float*)d_in[0];
    const float* k = (const float*)d_in[1];
    const float* v = (const float*)d_in[2];
    float* out = (float*)d_out;
    float* wts = out + (size_t)NH * NSEQ * EDIM;

    convert_kv<<<SCR_ELEMS / 4 / 512, 512>>>(k, v);   // 4096 blocks

    cudaFuncSetAttribute(chunked_attn_mma,
                         cudaFuncAttributeMaxDynamicSharedMemorySize, SM_TOTAL);
    dim3 grid(CHUNKN / MTILE, NCH, NH);   // 4 x 16 x 16 = 1024 CTAs
    chunked_attn_mma<<<grid, 256, SM_TOTAL>>>(q, out, wts);
}

// round 14
// speedup vs baseline: 1.0740x; 1.0740x over previous
#include <cuda_runtime.h>
#include <cuda_bf16.h>
#include <cstdint>
#include <math.h>

#define NH     16
#define NSEQ   8192
#define EDIM   64
#define CHUNKN 512
#define NCH    16
#define WCOLS  15872
#define MTILE  64
#define SCALE  0.125f

// ---- bf16 hi/lo scratch planes: [0]=Khi [1]=Klo [2]=Vhi [3]=Vlo ----
#define SCR_ELEMS (16u * 8192u * 64u)   // 8388608
__device__ __nv_bfloat16 g_scr[4][SCR_ELEMS];

// ---- SMEM map (K/V/Q rows: 144B stride; S rows: 2064B = 516 fp32) ----
#define SM_Q     0            // Q hi @0, lo @+9216 ; V buf0 aliases after Q-frag preload
#define SM_K0    18432        // K hi @+0, lo @+9216 ; V buf1 aliases in phase 3
#define SM_K1    36864
#define SM_S     55296        // 64 x 2064 = 132096
#define SM_SUMS  187392       // 4 x 64 fp32
#define SM_INV   188416       // 64 fp32
#define SM_TOTAL 188672
#define S_LDF    516          // S stride in floats

__device__ __forceinline__ uint32_t s2u(const void* p) {
    uint32_t a;
    asm("{ .reg .u64 t; cvta.to.shared.u64 t, %1; cvt.u32.u64 %0, t; }" : "=r"(a) : "l"(p));
    return a;
}
__device__ __forceinline__ void ldmx4(uint32_t addr, uint32_t* r) {
    asm volatile("ldmatrix.sync.aligned.m8n8.x4.shared.b16 {%0,%1,%2,%3}, [%4];"
                 : "=r"(r[0]), "=r"(r[1]), "=r"(r[2]), "=r"(r[3]) : "r"(addr));
}
__device__ __forceinline__ void ldmx2(uint32_t addr, uint32_t* r) {
    asm volatile("ldmatrix.sync.aligned.m8n8.x2.shared.b16 {%0,%1}, [%2];"
                 : "=r"(r[0]), "=r"(r[1]) : "r"(addr));
}
__device__ __forceinline__ void ldmx2t(uint32_t addr, uint32_t* r) {
    asm volatile("ldmatrix.sync.aligned.m8n8.x2.trans.shared.b16 {%0,%1}, [%2];"
                 : "=r"(r[0]), "=r"(r[1]) : "r"(addr));
}
__device__ __forceinline__ void mma16816(float* d, const uint32_t* a, const uint32_t* b) {
    asm volatile("mma.sync.aligned.m16n8k16.row.col.f32.bf16.bf16.f32 "
                 "{%0,%1,%2,%3},{%4,%5,%6,%7},{%8,%9},{%0,%1,%2,%3};"
                 : "+f"(d[0]), "+f"(d[1]), "+f"(d[2]), "+f"(d[3])
                 : "r"(a[0]), "r"(a[1]), "r"(a[2]), "r"(a[3]), "r"(b[0]), "r"(b[1]));
}
__device__ __forceinline__ uint32_t packbf(float lo, float hi) {
    uint32_t r;
    asm("cvt.rn.bf16x2.f32 %0, %1, %2;" : "=r"(r) : "f"(hi), "f"(lo));
    return r;
}
__device__ __forceinline__ float bfval(float x) {
    return __bfloat162float(__float2bfloat16(x));
}
__device__ __forceinline__ void cpa16(uint32_t dst, const void* src) {
    asm volatile("cp.async.cg.shared.global [%0], [%1], 16;" :: "r"(dst), "l"(src));
}
#define CP_COMMIT() asm volatile("cp.async.commit_group;" ::: "memory")
#define CP_WAIT(n)  asm volatile("cp.async.wait_group %0;" :: "n"(n) : "memory")

// =================== pre-kernel: fp32 -> bf16 hi/lo planes ===================
__global__ __launch_bounds__(512)
void convert_kv(const float* __restrict__ key, const float* __restrict__ value)
{
    uint32_t i = blockIdx.x * 512u + threadIdx.x;
    float4 kv = ((const float4*)key)[i];
    float4 vv = ((const float4*)value)[i];
    uint2 khi, klo, vhi, vlo;
    khi.x = packbf(kv.x, kv.y); khi.y = packbf(kv.z, kv.w);
    klo.x = packbf(kv.x - bfval(kv.x), kv.y - bfval(kv.y));
    klo.y = packbf(kv.z - bfval(kv.z), kv.w - bfval(kv.w));
    vhi.x = packbf(vv.x, vv.y); vhi.y = packbf(vv.z, vv.w);
    vlo.x = packbf(vv.x - bfval(vv.x), vv.y - bfval(vv.y));
    vlo.y = packbf(vv.z - bfval(vv.z), vv.w - bfval(vv.w));
    ((uint2*)g_scr[0])[i] = khi;
    ((uint2*)g_scr[1])[i] = klo;
    ((uint2*)g_scr[2])[i] = vhi;
    ((uint2*)g_scr[3])[i] = vlo;
}

// =================== main kernel: 512 thr, 64 q-rows/CTA, S in smem ===================
__global__ __launch_bounds__(512, 1)
void chunked_attn_mma(const float* __restrict__ query, float* __restrict__ out,
                      float* __restrict__ wts)
{
    extern __shared__ char smem[];
    const uint32_t sb = s2u(smem);
    float* Sf = (float*)(smem + SM_S);
    const int tid = threadIdx.x, lane = tid & 31, w = tid >> 5;
    const int s  = w & 3;             // 16-row strip
    const int q4 = w >> 2;            // 16-key quarter (p1) / 16-e quarter (p3)

    const int rt = 7 - blockIdx.x;    // long CTAs first
    const int n  = blockIdx.y, h = blockIdx.z;
    const int r0 = rt * MTILE;
    const int m  = (n == 0) ? 0 : n - 1;
    const int nslab = rt + 1;         // 64-key slabs
    const int jend  = 64 * nslab;
    const int W     = (n == 0) ? 512 : 1024;
    const int wcb   = (n == 0) ? 0 : 512 + (n - 1) * 1024;
    const int zstep = (((W - jend + nslab - 1) / nslab) + 3) & ~3;

    const float* qbase = query + ((size_t)h * NSEQ + (size_t)n * CHUNKN + r0) * EDIM;
    const uint32_t gjbase = (uint32_t)h * NSEQ + (uint32_t)m * CHUNKN;

    const uint32_t kb[2] = {sb + SM_K0, sb + SM_K1};
    const uint32_t vb[2] = {sb + SM_Q,  sb + SM_K0};

    // ---- prefetch K slab 0 (2 planes x 64 rows x 8 segs) ----
    for (int i = tid; i < 1024; i += 512) {
        int pl = i >> 9, rem = i & 511, row = rem >> 3, seg = rem & 7;
        cpa16(kb[0] + (uint32_t)pl * 9216 + (uint32_t)row * 144 + seg * 16,
              g_scr[pl] + ((size_t)(gjbase + row) << 6) + seg * 8);
    }
    CP_COMMIT();

    // ---- Q fill (64 rows, hi/lo, pre-scaled) ----
    for (int idx = tid; idx < 1024; idx += 512) {
        int row = idx >> 4, c4 = (idx & 15) << 2;
        float4 qv = *(const float4*)(qbase + (size_t)row * EDIM + c4);
        float f[4] = {qv.x * SCALE, qv.y * SCALE, qv.z * SCALE, qv.w * SCALE};
        uint2 hv, lv;
        hv.x = packbf(f[0], f[1]); hv.y = packbf(f[2], f[3]);
        lv.x = packbf(f[0] - bfval(f[0]), f[1] - bfval(f[1]));
        lv.y = packbf(f[2] - bfval(f[2]), f[3] - bfval(f[3]));
        uint32_t o = (uint32_t)row * 144 + (uint32_t)c4 * 2;
        *(uint2*)(smem + SM_Q + o) = hv;
        *(uint2*)(smem + SM_Q + 9216 + o) = lv;
    }
    __syncthreads();

    // ---- Q fragment preload (then Q smem is free for V buf0) ----
    uint32_t qh[4][4], ql[4][4];
    {
        const uint32_t aQ = sb + SM_Q + (uint32_t)((s * 16 + (lane & 15)) * 144 + (lane >> 4) * 16);
        #pragma unroll
        for (int kc = 0; kc < 4; kc++) {
            ldmx4(aQ + kc * 32, qh[kc]);
            ldmx4(aQ + 9216 + kc * 32, ql[kc]);
        }
    }
    __syncthreads();   // Q reads done -> V0 may overwrite

    // ---- prefetch V slab 0 into vb[0] (aliases Q) ----
    for (int i = tid; i < 1024; i += 512) {
        int pl = i >> 9, rem = i & 511, row = rem >> 3, seg = rem & 7;
        cpa16(vb[0] + (uint32_t)pl * 9216 + (uint32_t)row * 144 + seg * 16,
              g_scr[2 + pl] + ((size_t)(gjbase + row) << 6) + seg * 8);
    }
    CP_COMMIT();

    float rs0 = 0.f, rs1 = 0.f;
    const int rloc = s * 16 + (lane >> 2);     // local row of frag rows c0/c1
    const int rlo = r0 + rloc, rhi = rlo + 8;
    const uint32_t bKoff = (uint32_t)((q4 * 16 + (lane & 7)) * 144 + ((lane >> 3) & 1) * 16);
    const float4 z4 = make_float4(0.f, 0.f, 0.f, 0.f);
    const int strip_max = r0 + s * 16 + 15;

    // ==================== phase 1: GEMM1 -> exp -> S(smem) ; zero bands ====================
    for (int kt = 0; kt < nslab; kt++) {
        const int p = kt & 1;
        if (kt + 1 < nslab) {
            for (int i = tid; i < 1024; i += 512) {
                int pl = i >> 9, rem = i & 511, row = rem >> 3, seg = rem & 7;
                cpa16(kb[1 - p] + (uint32_t)pl * 9216 + (uint32_t)row * 144 + seg * 16,
                      g_scr[pl] + ((size_t)(gjbase + (kt + 1) * 64 + row) << 6) + seg * 8);
            }
            CP_COMMIT();
            CP_WAIT(1);
        } else {
            CP_WAIT(0);
        }
        __syncthreads();

        const bool slabDead = (kt * 64 > strip_max);
        const bool mmaDead  = (kt * 64 + q4 * 16 > strip_max);

        float sacc[2][4];
        #pragma unroll
        for (int t = 0; t < 2; t++)
            #pragma unroll
            for (int u = 0; u < 4; u++) sacc[t][u] = 0.f;

        if (!mmaDead) {
            const uint32_t bK = kb[p] + bKoff;
            #pragma unroll
            for (int kc = 0; kc < 4; kc++) {
                #pragma unroll
                for (int t = 0; t < 2; t++) {
                    uint32_t bh[2], bl[2];
                    uint32_t ba = bK + (uint32_t)t * 1152 + kc * 32;
                    ldmx2(ba, bh);
                    ldmx2(ba + 9216, bl);
                    mma16816(sacc[t], qh[kc], bh);
                    mma16816(sacc[t], qh[kc], bl);
                    mma16816(sacc[t], ql[kc], bh);
                }
            }
        }
        if (!slabDead) {
            const int cb = kt * 64 + q4 * 16 + 2 * (lane & 3);
            #pragma unroll
            for (int t = 0; t < 2; t++) {
                int c = cb + t * 8;
                float p00 = (c     <= rlo) ? __expf(sacc[t][0]) : 0.f;
                float p01 = (c + 1 <= rlo) ? __expf(sacc[t][1]) : 0.f;
                float p10 = (c     <= rhi) ? __expf(sacc[t][2]) : 0.f;
                float p11 = (c + 1 <= rhi) ? __expf(sacc[t][3]) : 0.f;
                rs0 += p00 + p01;  rs1 += p10 + p11;
                *(float2*)&Sf[rloc * S_LDF + c]       = make_float2(p00, p01);
                *(float2*)&Sf[(rloc + 8) * S_LDF + c] = make_float2(p10, p11);
            }
        }
        // zero band for this slab (rows w*4..+3)
        {
            int z0 = jend + kt * zstep;
            int z1 = z0 + zstep; if (z1 > W) z1 = W;
            #pragma unroll
            for (int rr = 0; rr < 4; rr++) {
                float* wr = wts + ((size_t)h * CHUNKN + r0 + w * 4 + rr) * WCOLS + wcb;
                for (int c = z0 + lane * 4; c < z1; c += 128)
                    __stcs((float4*)(wr + c), z4);
            }
        }
        __syncthreads();
    }

    // ==================== phase 2: rowsums -> inv ====================
    rs0 += __shfl_xor_sync(0xffffffffu, rs0, 1);
    rs0 += __shfl_xor_sync(0xffffffffu, rs0, 2);
    rs1 += __shfl_xor_sync(0xffffffffu, rs1, 1);
    rs1 += __shfl_xor_sync(0xffffffffu, rs1, 2);
    if ((lane & 3) == 0) {
        float* su = (float*)(smem + SM_SUMS);
        su[q4 * 64 + s * 16 + (lane >> 2)]     = rs0;
        su[q4 * 64 + s * 16 + (lane >> 2) + 8] = rs1;
    }
    __syncthreads();
    if (tid < 64) {
        const float* su = (const float*)(smem + SM_SUMS);
        ((float*)(smem + SM_INV))[tid] =
            1.f / (su[tid] + su[64 + tid] + su[128 + tid] + su[192 + tid]);
    }
    __syncthreads();
    const float* invp = (const float*)(smem + SM_INV);

    // ==================== phase 3: GEMM2 + one-pass normalized weights store ====================
    float oacc[2][4];
    #pragma unroll
    for (int t = 0; t < 2; t++)
        #pragma unroll
        for (int u = 0; u < 4; u++) oacc[t][u] = 0.f;

    for (int kt = 0; kt < nslab; kt++) {
        const int pv = kt & 1;
        if (kt + 1 < nslab) {
            for (int i = tid; i < 1024; i += 512) {
                int pl = i >> 9, rem = i & 511, row = rem >> 3, seg = rem & 7;
                cpa16(vb[1 - pv] + (uint32_t)pl * 9216 + (uint32_t)row * 144 + seg * 16,
                      g_scr[2 + pl] + ((size_t)(gjbase + (kt + 1) * 64 + row) << 6) + seg * 8);
            }
            CP_COMMIT();
            CP_WAIT(1);
        } else {
            CP_WAIT(0);
        }
        __syncthreads();

        const bool slabDead = (kt * 64 > strip_max);
        if (!slabDead) {
            #pragma unroll
            for (int ks = 0; ks < 4; ks++) {
                const int ck = kt * 64 + ks * 16 + 2 * (lane & 3);
                float2 l0 = *(float2*)&Sf[rloc * S_LDF + ck];
                float2 l1 = *(float2*)&Sf[(rloc + 8) * S_LDF + ck];
                float2 l2 = *(float2*)&Sf[rloc * S_LDF + ck + 8];
                float2 l3 = *(float2*)&Sf[(rloc + 8) * S_LDF + ck + 8];
                uint32_t ah[4] = {packbf(l0.x, l0.y), packbf(l1.x, l1.y),
                                  packbf(l2.x, l2.y), packbf(l3.x, l3.y)};
                uint32_t al[4] = {packbf(l0.x - bfval(l0.x), l0.y - bfval(l0.y)),
                                  packbf(l1.x - bfval(l1.x), l1.y - bfval(l1.y)),
                                  packbf(l2.x - bfval(l2.x), l2.y - bfval(l2.y)),
                                  packbf(l3.x - bfval(l3.x), l3.y - bfval(l3.y))};
                #pragma unroll
                for (int t2 = 0; t2 < 2; t2++) {
                    uint32_t bh[2], bl[2];
                    uint32_t ba = vb[pv] + (uint32_t)((ks * 16 + (lane & 15)) * 144
                                + (q4 * 16 + t2 * 8) * 2);
                    ldmx2t(ba, bh);
                    ldmx2t(ba + 9216, bl);
                    mma16816(oacc[t2], ah, bh);
                    mma16816(oacc[t2], ah, bl);
                    mma16816(oacc[t2], al, bh);
                }
            }
        }
        // live weights band: rows w*4..+3, cols [kt*64, kt*64+64), coalesced STG.128
        {
            const bool gDead = (kt * 64 > r0 + (w >> 2) * 16 + 15);
            #pragma unroll
            for (int pass = 0; pass < 2; pass++) {
                int row = w * 4 + pass * 2 + (lane >> 4);
                float iv = invp[row];
                float4 o = z4;
                if (!gDead) {
                    float4 sv = *(float4*)&Sf[row * S_LDF + kt * 64 + (lane & 15) * 4];
                    o = make_float4(sv.x * iv, sv.y * iv, sv.z * iv, sv.w * iv);
                }
                __stcs((float4*)(wts + ((size_t)h * CHUNKN + r0 + row) * WCOLS + wcb
                                 + kt * 64 + (lane & 15) * 4), o);
            }
        }
        __syncthreads();
    }

    // ==================== O epilogue (warp-exclusive tiles) ====================
    {
        float iv0 = invp[rloc], iv1 = invp[rloc + 8];
        float* op = out + ((size_t)h * NSEQ + (size_t)n * CHUNKN + rlo) * EDIM
                  + q4 * 16 + 2 * (lane & 3);
        #pragma unroll
        for (int t2 = 0; t2 < 2; t2++) {
            __stcs((float2*)(op + t2 * 8),
                   make_float2(oacc[t2][0] * iv0, oacc[t2][1] * iv0));
            __stcs((float2*)(op + (size_t)8 * EDIM + t2 * 8),
                   make_float2(oacc[t2][2] * iv1, oacc[t2][3] * iv1));
        }
    }
}

extern "C" void kernel_launch(void* const* d_in, const int* in_sizes, int n_in,
                              void* d_out, int out_size)
{
    const float* q = (const float*)d_in[0];
    const float* k = (const float*)d_in[1];
    const float* v = (const float*)d_in[2];
    float* out = (float*)d_out;
    float* wts = out + (size_t)NH * NSEQ * EDIM;

    convert_kv<<<SCR_ELEMS / 4 / 512, 512>>>(k, v);   // 4096 blocks

    cudaFuncSetAttribute(chunked_attn_mma,
                         cudaFuncAttributeMaxDynamicSharedMemorySize, SM_TOTAL);
    dim3 grid(CHUNKN / MTILE, NCH, NH);   // 8 x 16 x 16 = 2048 CTAs
    chunked_attn_mma<<<grid, 512, SM_TOTAL>>>(q, out, wts);
}

// round 15
// speedup vs baseline: 1.1279x; 1.0502x over previous
#include <cuda_runtime.h>
#include <cuda_bf16.h>
#include <cstdint>
#include <math.h>

#define NH     16
#define NSEQ   8192
#define EDIM   64
#define CHUNKN 512
#define NCH    16
#define WCOLS  15872
#define MTILE  64
#define QSCALE 0.180336884f   // 0.125 * log2(e)

// ---- bf16 hi/lo scratch planes: [0]=Khi [1]=Klo [2]=Vhi [3]=Vlo ----
#define SCR_ELEMS (16u * 8192u * 64u)   // 8388608
__device__ __nv_bfloat16 g_scr[4][SCR_ELEMS];

// ---- SMEM map ----
// Q/K/V rows: 144B stride (64 bf16 + 8 pad), hi plane @+0, lo @+9216.
// S planes: 64 rows x 1040B (512 bf16 + 16B pad), hi and lo.
#define SM_Q     0
#define SM_K0    18432
#define SM_K1    36864
#define SM_SH    55296
#define SM_SL    121856
#define SM_SUMS  188416
#define SM_INV   189440
#define SM_TOTAL 189696
#define SH_LDB   1040

__device__ __forceinline__ uint32_t s2u(const void* p) {
    uint32_t a;
    asm("{ .reg .u64 t; cvta.to.shared.u64 t, %1; cvt.u32.u64 %0, t; }" : "=r"(a) : "l"(p));
    return a;
}
__device__ __forceinline__ void ldmx4(uint32_t addr, uint32_t* r) {
    asm volatile("ldmatrix.sync.aligned.m8n8.x4.shared.b16 {%0,%1,%2,%3}, [%4];"
                 : "=r"(r[0]), "=r"(r[1]), "=r"(r[2]), "=r"(r[3]) : "r"(addr));
}
__device__ __forceinline__ void ldmx4t(uint32_t addr, uint32_t* r) {
    asm volatile("ldmatrix.sync.aligned.m8n8.x4.trans.shared.b16 {%0,%1,%2,%3}, [%4];"
                 : "=r"(r[0]), "=r"(r[1]), "=r"(r[2]), "=r"(r[3]) : "r"(addr));
}
__device__ __forceinline__ void mma16816(float* d, const uint32_t* a, const uint32_t* b) {
    asm volatile("mma.sync.aligned.m16n8k16.row.col.f32.bf16.bf16.f32 "
                 "{%0,%1,%2,%3},{%4,%5,%6,%7},{%8,%9},{%0,%1,%2,%3};"
                 : "+f"(d[0]), "+f"(d[1]), "+f"(d[2]), "+f"(d[3])
                 : "r"(a[0]), "r"(a[1]), "r"(a[2]), "r"(a[3]), "r"(b[0]), "r"(b[1]));
}
__device__ __forceinline__ uint32_t packbf(float lo, float hi) {
    uint32_t r;
    asm("cvt.rn.bf16x2.f32 %0, %1, %2;" : "=r"(r) : "f"(hi), "f"(lo));
    return r;
}
__device__ __forceinline__ float bfval(float x) {
    return __bfloat162float(__float2bfloat16(x));
}
__device__ __forceinline__ float ex2(float x) {
    float y;
    asm("ex2.approx.f32 %0, %1;" : "=f"(y) : "f"(x));
    return y;
}
__device__ __forceinline__ void cpa16(uint32_t dst, const void* src) {
    asm volatile("cp.async.cg.shared.global [%0], [%1], 16;" :: "r"(dst), "l"(src));
}
#define CP_COMMIT() asm volatile("cp.async.commit_group;" ::: "memory")
#define CP_WAIT(n)  asm volatile("cp.async.wait_group %0;" :: "n"(n) : "memory")

// =================== pre-kernel: fp32 -> bf16 hi/lo planes ===================
__global__ __launch_bounds__(512)
void convert_kv(const float* __restrict__ key, const float* __restrict__ value)
{
    uint32_t i = blockIdx.x * 512u + threadIdx.x;
    float4 kv = ((const float4*)key)[i];
    float4 vv = ((const float4*)value)[i];
    uint2 khi, klo, vhi, vlo;
    khi.x = packbf(kv.x, kv.y); khi.y = packbf(kv.z, kv.w);
    klo.x = packbf(kv.x - bfval(kv.x), kv.y - bfval(kv.y));
    klo.y = packbf(kv.z - bfval(kv.z), kv.w - bfval(kv.w));
    vhi.x = packbf(vv.x, vv.y); vhi.y = packbf(vv.z, vv.w);
    vlo.x = packbf(vv.x - bfval(vv.x), vv.y - bfval(vv.y));
    vlo.y = packbf(vv.z - bfval(vv.z), vv.w - bfval(vv.w));
    ((uint2*)g_scr[0])[i] = khi;
    ((uint2*)g_scr[1])[i] = klo;
    ((uint2*)g_scr[2])[i] = vhi;
    ((uint2*)g_scr[3])[i] = vlo;
}

// =================== main kernel: 512 thr, 64 q-rows/CTA, S(bf16 hi/lo) in smem ===================
__global__ __launch_bounds__(512, 1)
void chunked_attn_mma(const float* __restrict__ query, float* __restrict__ out,
                      float* __restrict__ wts)
{
    extern __shared__ char smem[];
    const uint32_t sb = s2u(smem);
    const int tid = threadIdx.x, lane = tid & 31, w = tid >> 5;
    const int s  = w & 3;             // 16-row strip
    const int q4 = w >> 2;            // 16-key quarter (p1) / 16-e quarter (p3)

    const int rt = 7 - blockIdx.x;    // long CTAs first
    const int n  = blockIdx.y, h = blockIdx.z;
    const int r0 = rt * MTILE;
    const int m  = (n == 0) ? 0 : n - 1;
    const int nslab = rt + 1;         // 64-key slabs
    const int jend  = 64 * nslab;
    const int W     = (n == 0) ? 512 : 1024;
    const int wcb   = (n == 0) ? 0 : 512 + (n - 1) * 1024;
    const int zstep = (((W - jend + nslab - 1) / nslab) + 3) & ~3;

    const float* qbase = query + ((size_t)h * NSEQ + (size_t)n * CHUNKN + r0) * EDIM;
    const uint32_t gjbase = (uint32_t)h * NSEQ + (uint32_t)m * CHUNKN;

    const uint32_t kb[2] = {sb + SM_K0, sb + SM_K1};
    const uint32_t vb[2] = {sb + SM_Q,  sb + SM_K0};

    // ---- prefetch K slab 0 (hi+lo planes) ----
    for (int i = tid; i < 1024; i += 512) {
        int pl = i >> 9, rem = i & 511, row = rem >> 3, seg = rem & 7;
        cpa16(kb[0] + (uint32_t)pl * 9216 + (uint32_t)row * 144 + seg * 16,
              g_scr[pl] + ((size_t)(gjbase + row) << 6) + seg * 8);
    }
    CP_COMMIT();

    // ---- Q fill (64 rows, hi/lo, pre-scaled by 0.125*log2e) ----
    for (int idx = tid; idx < 1024; idx += 512) {
        int row = idx >> 4, c4 = (idx & 15) << 2;
        float4 qv = *(const float4*)(qbase + (size_t)row * EDIM + c4);
        float f[4] = {qv.x * QSCALE, qv.y * QSCALE, qv.z * QSCALE, qv.w * QSCALE};
        uint2 hv, lv;
        hv.x = packbf(f[0], f[1]); hv.y = packbf(f[2], f[3]);
        lv.x = packbf(f[0] - bfval(f[0]), f[1] - bfval(f[1]));
        lv.y = packbf(f[2] - bfval(f[2]), f[3] - bfval(f[3]));
        uint32_t o = (uint32_t)row * 144 + (uint32_t)c4 * 2;
        *(uint2*)(smem + SM_Q + o) = hv;
        *(uint2*)(smem + SM_Q + 9216 + o) = lv;
    }
    __syncthreads();

    // ---- Q fragment preload (then Q smem is free for V buf0) ----
    uint32_t qh[4][4], ql[4][4];
    {
        const uint32_t aQ = sb + SM_Q + (uint32_t)((s * 16 + (lane & 15)) * 144 + (lane >> 4) * 16);
        #pragma unroll
        for (int kc = 0; kc < 4; kc++) {
            ldmx4(aQ + kc * 32, qh[kc]);
            ldmx4(aQ + 9216 + kc * 32, ql[kc]);
        }
    }
    __syncthreads();   // Q reads done -> V0 may overwrite

    // ---- prefetch V slab 0 into vb[0] (aliases Q) ----
    for (int i = tid; i < 1024; i += 512) {
        int pl = i >> 9, rem = i & 511, row = rem >> 3, seg = rem & 7;
        cpa16(vb[0] + (uint32_t)pl * 9216 + (uint32_t)row * 144 + seg * 16,
              g_scr[2 + pl] + ((size_t)(gjbase + row) << 6) + seg * 8);
    }
    CP_COMMIT();

    float rs0 = 0.f, rs1 = 0.f;
    const int rloc = s * 16 + (lane >> 2);
    const int rlo = r0 + rloc, rhi = rlo + 8;
    // fused hi/lo ldmx4: lanes 0-15 -> hi plane, 16-31 -> lo plane
    const uint32_t bKoff = (uint32_t)((q4 * 16 + (lane & 7)) * 144
                          + ((lane >> 3) & 1) * 16 + (lane >> 4) * 9216);
    const uint32_t bVoff = (uint32_t)((lane & 15) * 144 + (lane >> 4) * 9216);
    const float4 z4 = make_float4(0.f, 0.f, 0.f, 0.f);
    const int strip_max = r0 + s * 16 + 15;

    // ==================== phase 1: GEMM1 -> ex2 -> S planes ; zero bands ====================
    for (int kt = 0; kt < nslab; kt++) {
        const int p = kt & 1;
        if (kt + 1 < nslab) {
            for (int i = tid; i < 1024; i += 512) {
                int pl = i >> 9, rem = i & 511, row = rem >> 3, seg = rem & 7;
                cpa16(kb[1 - p] + (uint32_t)pl * 9216 + (uint32_t)row * 144 + seg * 16,
                      g_scr[pl] + ((size_t)(gjbase + (kt + 1) * 64 + row) << 6) + seg * 8);
            }
            CP_COMMIT();
            CP_WAIT(1);
        } else {
            CP_WAIT(0);
        }
        __syncthreads();

        const bool slabDead = (kt * 64 > strip_max);
        const bool mmaDead  = (kt * 64 + q4 * 16 > strip_max);

        float sacc[2][4];
        #pragma unroll
        for (int t = 0; t < 2; t++)
            #pragma unroll
            for (int u = 0; u < 4; u++) sacc[t][u] = 0.f;

        if (!mmaDead) {
            const uint32_t bK = kb[p] + bKoff;
            #pragma unroll
            for (int kc = 0; kc < 4; kc++) {
                #pragma unroll
                for (int t = 0; t < 2; t++) {
                    uint32_t r4[4];
                    ldmx4(bK + (uint32_t)t * 1152 + kc * 32, r4);  // r4[0..1]=hi, r4[2..3]=lo
                    mma16816(sacc[t], qh[kc], r4);
                    mma16816(sacc[t], qh[kc], r4 + 2);
                    mma16816(sacc[t], ql[kc], r4);
                }
            }
        }
        if (!slabDead) {
            const int cb = kt * 64 + q4 * 16 + 2 * (lane & 3);
            #pragma unroll
            for (int t = 0; t < 2; t++) {
                int c = cb + t * 8;
                float p00 = (c     <= rlo) ? ex2(sacc[t][0]) : 0.f;
                float p01 = (c + 1 <= rlo) ? ex2(sacc[t][1]) : 0.f;
                float p10 = (c     <= rhi) ? ex2(sacc[t][2]) : 0.f;
                float p11 = (c + 1 <= rhi) ? ex2(sacc[t][3]) : 0.f;
                rs0 += p00 + p01;  rs1 += p10 + p11;
                uint32_t off = (uint32_t)c * 2;
                *(uint32_t*)(smem + SM_SH + (uint32_t)rloc * SH_LDB + off) = packbf(p00, p01);
                *(uint32_t*)(smem + SM_SH + (uint32_t)(rloc + 8) * SH_LDB + off) = packbf(p10, p11);
                *(uint32_t*)(smem + SM_SL + (uint32_t)rloc * SH_LDB + off) =
                    packbf(p00 - bfval(p00), p01 - bfval(p01));
                *(uint32_t*)(smem + SM_SL + (uint32_t)(rloc + 8) * SH_LDB + off) =
                    packbf(p10 - bfval(p10), p11 - bfval(p11));
            }
        }
        // zero band for this slab (rows w*4..+3)
        {
            int z0 = jend + kt * zstep;
            int z1 = z0 + zstep; if (z1 > W) z1 = W;
            #pragma unroll
            for (int rr = 0; rr < 4; rr++) {
                float* wr = wts + ((size_t)h * CHUNKN + r0 + w * 4 + rr) * WCOLS + wcb;
                for (int c = z0 + lane * 4; c < z1; c += 128)
                    __stcs((float4*)(wr + c), z4);
            }
        }
        __syncthreads();
    }

    // ==================== phase 2: rowsums -> inv ====================
    rs0 += __shfl_xor_sync(0xffffffffu, rs0, 1);
    rs0 += __shfl_xor_sync(0xffffffffu, rs0, 2);
    rs1 += __shfl_xor_sync(0xffffffffu, rs1, 1);
    rs1 += __shfl_xor_sync(0xffffffffu, rs1, 2);
    if ((lane & 3) == 0) {
        float* su = (float*)(smem + SM_SUMS);
        su[q4 * 64 + s * 16 + (lane >> 2)]     = rs0;
        su[q4 * 64 + s * 16 + (lane >> 2) + 8] = rs1;
    }
    __syncthreads();
    if (tid < 64) {
        const float* su = (const float*)(smem + SM_SUMS);
        ((float*)(smem + SM_INV))[tid] =
            1.f / (su[tid] + su[64 + tid] + su[128 + tid] + su[192 + tid]);
    }
    __syncthreads();
    const float* invp = (const float*)(smem + SM_INV);

    // ==================== phase 3: GEMM2 + one-pass normalized weights store ====================
    float oacc[2][4];
    #pragma unroll
    for (int t = 0; t < 2; t++)
        #pragma unroll
        for (int u = 0; u < 4; u++) oacc[t][u] = 0.f;

    for (int kt = 0; kt < nslab; kt++) {
        const int pv = kt & 1;
        if (kt + 1 < nslab) {
            for (int i = tid; i < 1024; i += 512) {
                int pl = i >> 9, rem = i & 511, row = rem >> 3, seg = rem & 7;
                cpa16(vb[1 - pv] + (uint32_t)pl * 9216 + (uint32_t)row * 144 + seg * 16,
                      g_scr[2 + pl] + ((size_t)(gjbase + (kt + 1) * 64 + row) << 6) + seg * 8);
            }
            CP_COMMIT();
            CP_WAIT(1);
        } else {
            CP_WAIT(0);
        }
        __syncthreads();

        const bool slabDead = (kt * 64 > strip_max);
        if (!slabDead) {
            #pragma unroll
            for (int ks = 0; ks < 4; ks++) {
                const uint32_t off = (uint32_t)(kt * 64 + ks * 16 + 2 * (lane & 3)) * 2;
                uint32_t ah[4], al[4];
                ah[0] = *(const uint32_t*)(smem + SM_SH + (uint32_t)rloc * SH_LDB + off);
                ah[1] = *(const uint32_t*)(smem + SM_SH + (uint32_t)(rloc + 8) * SH_LDB + off);
                ah[2] = *(const uint32_t*)(smem + SM_SH + (uint32_t)rloc * SH_LDB + off + 16);
                ah[3] = *(const uint32_t*)(smem + SM_SH + (uint32_t)(rloc + 8) * SH_LDB + off + 16);
                al[0] = *(const uint32_t*)(smem + SM_SL + (uint32_t)rloc * SH_LDB + off);
                al[1] = *(const uint32_t*)(smem + SM_SL + (uint32_t)(rloc + 8) * SH_LDB + off);
                al[2] = *(const uint32_t*)(smem + SM_SL + (uint32_t)rloc * SH_LDB + off + 16);
                al[3] = *(const uint32_t*)(smem + SM_SL + (uint32_t)(rloc + 8) * SH_LDB + off + 16);
                #pragma unroll
                for (int t2 = 0; t2 < 2; t2++) {
                    uint32_t r4[4];
                    ldmx4t(vb[pv] + bVoff + (uint32_t)(ks * 16) * 144
                           + (uint32_t)(q4 * 16 + t2 * 8) * 2, r4);
                    mma16816(oacc[t2], ah, r4);
                    mma16816(oacc[t2], ah, r4 + 2);
                    mma16816(oacc[t2], al, r4);
                }
            }
        }
        // live weights band: rows w*4..+3, cols [kt*64, +64), one-pass normalized STG.128
        {
            const bool gDead = (kt * 64 > r0 + (w >> 2) * 16 + 15);
            #pragma unroll
            for (int pass = 0; pass < 2; pass++) {
                int row = w * 4 + pass * 2 + (lane >> 4);
                float iv = invp[row];
                float4 o = z4;
                if (!gDead) {
                    uint32_t soff = (uint32_t)row * SH_LDB
                                  + (uint32_t)(kt * 64 + (lane & 15) * 4) * 2;
                    uint2 hw = *(const uint2*)(smem + SM_SH + soff);
                    uint2 lw = *(const uint2*)(smem + SM_SL + soff);
                    float2 a0 = __bfloat1622float2(*(__nv_bfloat162*)&hw.x);
                    float2 b0 = __bfloat1622float2(*(__nv_bfloat162*)&lw.x);
                    float2 a1 = __bfloat1622float2(*(__nv_bfloat162*)&hw.y);
                    float2 b1 = __bfloat1622float2(*(__nv_bfloat162*)&lw.y);
                    o = make_float4((a0.x + b0.x) * iv, (a0.y + b0.y) * iv,
                                    (a1.x + b1.x) * iv, (a1.y + b1.y) * iv);
                }
                __stcs((float4*)(wts + ((size_t)h * CHUNKN + r0 + row) * WCOLS + wcb
                                 + kt * 64 + (lane & 15) * 4), o);
            }
        }
        __syncthreads();
    }

    // ==================== O epilogue (warp-exclusive tiles) ====================
    {
        float iv0 = invp[rloc], iv1 = invp[rloc + 8];
        float* op = out + ((size_t)h * NSEQ + (size_t)n * CHUNKN + rlo) * EDIM
                  + q4 * 16 + 2 * (lane & 3);
        #pragma unroll
        for (int t2 = 0; t2 < 2; t2++) {
            __stcs((float2*)(op + t2 * 8),
                   make_float2(oacc[t2][0] * iv0, oacc[t2][1] * iv0));
            __stcs((float2*)(op + (size_t)8 * EDIM + t2 * 8),
                   make_float2(oacc[t2][2] * iv1, oacc[t2][3] * iv1));
        }
    }
}

extern "C" void kernel_launch(void* const* d_in, const int* in_sizes, int n_in,
                              void* d_out, int out_size)
{
    const float* q = (const float*)d_in[0];
    const float* k = (const float*)d_in[1];
    const float* v = (const float*)d_in[2];
    float* out = (float*)d_out;
    float* wts = out + (size_t)NH * NSEQ * EDIM;

    convert_kv<<<SCR_ELEMS / 4 / 512, 512>>>(k, v);   // 4096 blocks

    cudaFuncSetAttribute(chunked_attn_mma,
                         cudaFuncAttributeMaxDynamicSharedMemorySize, SM_TOTAL);
    dim3 grid(CHUNKN / MTILE, NCH, NH);   // 8 x 16 x 16 = 2048 CTAs
    chunked_attn_mma<<<grid, 512, SM_TOTAL>>>(q, out, wts);
}